// round 6
// baseline (speedup 1.0000x reference)
#include <cuda_runtime.h>
#include <cstdint>

#define BB 4
#define SQ 4
#define HH 32
#define HKV 8
#define GG 4
#define DD 128
#define DVV 128
#define SMAX 8192
#define RR 16
#define TT 32
#define NSPLIT 32
#define CHUNK (SMAX / NSPLIT)
#define NTHREADS 128
#define SCALE 0.08838834764831845f

// smem layout (bytes)
#define SMEM_Q_OFF 0
#define SMEM_K_OFF 8192
#define SMEM_V_OFF (8192 + 32768)
#define SMEM_PD_OFF (8192 + 32768 + 32768)   // [16][34] float2 = 4352
#define SMEM_C_OFF (SMEM_PD_OFF + 4352)      // sC 16 float
#define SMEM_BYTES (SMEM_C_OFF + 64)

typedef unsigned long long u64;

__device__ __forceinline__ void fma2(u64& d, u64 a, u64 b) {
    asm("fma.rn.f32x2 %0, %1, %2, %0;" : "+l"(d) : "l"(a), "l"(b));
}
__device__ __forceinline__ void mul2(u64& d, u64 a) {
    asm("mul.rn.f32x2 %0, %0, %1;" : "+l"(d) : "l"(a));
}
__device__ __forceinline__ u64 pack2(float x) {
    u64 r; asm("mov.b64 %0, {%1, %1};" : "=l"(r) : "f"(x)); return r;
}
__device__ __forceinline__ float2 unpack2(u64 a) {
    float2 f; asm("mov.b64 {%0, %1}, %2;" : "=f"(f.x), "=f"(f.y) : "l"(a)); return f;
}

// split-K partial scratch (static device memory; no allocation)
__device__ float g_po[(size_t)BB * HKV * NSPLIT * RR * DVV];
__device__ float g_pm[BB * HKV * NSPLIT * RR];
__device__ float g_pl[BB * HKV * NSPLIT * RR];

extern "C" __global__ void __launch_bounds__(NTHREADS, 2)
attn_split_kernel(const float* __restrict__ Q, const float* __restrict__ K,
                  const float* __restrict__ V, const int* __restrict__ seqlens)
{
    extern __shared__ char smem[];
    float4* qs4 = (float4*)(smem + SMEM_Q_OFF);
    float4* ks4 = (float4*)(smem + SMEM_K_OFF);
    float4* vs4 = (float4*)(smem + SMEM_V_OFF);
    float2* sPd = (float2*)(smem + SMEM_PD_OFF);   // [r][34]
    float*  sC  = (float*)(smem + SMEM_C_OFF);

    const int split = blockIdx.x;
    const int hkv   = blockIdx.y;
    const int b     = blockIdx.z;
    const int tid   = threadIdx.x;
    const int lane  = tid & 31;
    const int wid   = tid >> 5;

    const int L  = seqlens[b];
    const int c0 = split * CHUNK;
    int n_eff = L - c0;
    if (n_eff > CHUNK) n_eff = CHUNK;
    const int part = (b * HKV + hkv) * NSPLIT + split;

    // QK/softmax ownership: warp owns rows R..R+3, full d, lane = token
    const int R = wid * 4;
    // PV ownership: warp owns d-cols [32*wid, 32*wid+32)
    const int pr   = lane >> 1;
    const int pd   = (wid << 5) + ((lane & 1) << 4);
    const int vidx = pd >> 2;

    float m[4], l[4];
#pragma unroll
    for (int i = 0; i < 4; i++) { m[i] = -1e30f; l[i] = 0.f; }
    u64 o[8];
#pragma unroll
    for (int i = 0; i < 8; i++) o[i] = 0ull;

    if (n_eff > 0) {
        // ---- Q (pre-scaled) into smem ----
#pragma unroll
        for (int i = 0; i < 4; i++) {
            int f  = i * NTHREADS + tid;
            int r  = f >> 5;
            int d4 = f & 31;
            int h  = hkv * GG + (r >> 2);
            int mm = r & 3;
            const float4 qv = *(const float4*)(Q + ((size_t)((b * SQ + mm) * HH + h)) * DD + d4 * 4);
            float4 qq;
            qq.x = qv.x * SCALE; qq.y = qv.y * SCALE;
            qq.z = qv.z * SCALE; qq.w = qv.w * SCALE;
            qs4[f] = qq;
        }

        const int ntiles = (n_eff + TT - 1) / TT;
        const size_t kvbase = ((size_t)b * SMAX * HKV + hkv) * DD;

        auto issue_tile = [&](int it) {
            const int jb   = c0 + it * TT;
            const int bufo = (it & 1) * (TT * 32);
#pragma unroll
            for (int i = 0; i < 8; i++) {
                int f  = i * NTHREADS + tid;   // 0..1023
                int t  = f >> 5;
                int d4 = f & 31;
                const float* gk = K + kvbase + (size_t)(jb + t) * (HKV * DD) + d4 * 4;
                const float* gv = V + kvbase + (size_t)(jb + t) * (HKV * DD) + d4 * 4;
                unsigned ka = (unsigned)__cvta_generic_to_shared(&ks4[bufo + t * 32 + (d4 ^ t)]);
                unsigned va = (unsigned)__cvta_generic_to_shared(&vs4[bufo + t * 32 + d4]);
                asm volatile("cp.async.cg.shared.global [%0], [%1], 16;\n" :: "r"(ka), "l"(gk));
                asm volatile("cp.async.cg.shared.global [%0], [%1], 16;\n" :: "r"(va), "l"(gv));
            }
            asm volatile("cp.async.commit_group;\n" ::: "memory");
        };

        issue_tile(0);
        if (ntiles > 1) issue_tile(1);

        const int tok0 = c0 + lane;   // token this lane handles (plus it*TT)

        for (int it = 0; it < ntiles; ++it) {
            if (it < ntiles - 1) asm volatile("cp.async.wait_group 1;\n" ::: "memory");
            else                 asm volatile("cp.async.wait_group 0;\n" ::: "memory");
            __syncthreads();   // A: tile data visible to all warps (also Q on it==0)

            const int bufo = (it & 1) * (TT * 32);

            // ---- S = Q K^T : 4 rows x 1 token/thread, full d=128, packed pairs ----
            u64 acc[4];
#pragma unroll
            for (int rr = 0; rr < 4; rr++) acc[rr] = 0ull;
            {
                const ulonglong2* kb = (const ulonglong2*)(ks4 + bufo);
                const ulonglong2* qb = (const ulonglong2*)qs4;
#pragma unroll
                for (int d4 = 0; d4 < 32; d4++) {
                    ulonglong2 k = kb[lane * 32 + (d4 ^ lane)];
#pragma unroll
                    for (int rr = 0; rr < 4; rr++) {
                        ulonglong2 q = qb[(R + rr) * 32 + d4];
                        fma2(acc[rr], q.x, k.x);
                        fma2(acc[rr], q.y, k.y);
                    }
                }
            }

            // ---- in-warp online softmax for rows R..R+3 ----
            {
                const int tok = tok0 + it * TT;
                float s[4], mx[4];
#pragma unroll
                for (int rr = 0; rr < 4; rr++) {
                    float2 f = unpack2(acc[rr]);
                    s[rr] = f.x + f.y;
                    if (tok > L - SQ + rr) s[rr] = -1e30f;
                    mx[rr] = s[rr];
                }
#pragma unroll
                for (int off = 16; off >= 1; off >>= 1) {
#pragma unroll
                    for (int rr = 0; rr < 4; rr++)
                        mx[rr] = fmaxf(mx[rr], __shfl_xor_sync(0xffffffffu, mx[rr], off));
                }
                float p[4], corr[4], sum[4];
#pragma unroll
                for (int rr = 0; rr < 4; rr++) {
                    float nm = fmaxf(m[rr], mx[rr]);
                    p[rr]    = __expf(s[rr] - nm);
                    corr[rr] = __expf(m[rr] - nm);
                    m[rr]    = nm;
                    sum[rr]  = p[rr];
                }
#pragma unroll
                for (int off = 16; off >= 1; off >>= 1) {
#pragma unroll
                    for (int rr = 0; rr < 4; rr++)
                        sum[rr] += __shfl_xor_sync(0xffffffffu, sum[rr], off);
                }
#pragma unroll
                for (int rr = 0; rr < 4; rr++) {
                    l[rr] = l[rr] * corr[rr] + sum[rr];
                    sPd[(R + rr) * 34 + lane] = make_float2(p[rr], p[rr]);
                }
                if (lane == 0) {
                    sC[R + 0] = corr[0]; sC[R + 1] = corr[1];
                    sC[R + 2] = corr[2]; sC[R + 3] = corr[3];
                }
            }
            __syncthreads();   // B: P + corr ready

            // ---- O += P V (packed dim-pairs, 2 tokens per p-load) ----
            {
                u64 cc = pack2(sC[pr]);
#pragma unroll
                for (int i = 0; i < 8; i++) mul2(o[i], cc);
                const ulonglong2* vb = (const ulonglong2*)(vs4 + bufo);
                const ulonglong2* pp = (const ulonglong2*)sPd;
#pragma unroll 4
                for (int tp = 0; tp < 16; tp++) {
                    ulonglong2 p2 = pp[pr * 17 + tp];   // {p_t0,p_t0},{p_t1,p_t1}
                    const int t0 = 2 * tp;
                    ulonglong2 v0 = vb[t0 * 32 + vidx];
                    ulonglong2 v1 = vb[t0 * 32 + vidx + 1];
                    ulonglong2 v2 = vb[t0 * 32 + vidx + 2];
                    ulonglong2 v3 = vb[t0 * 32 + vidx + 3];
                    fma2(o[0], p2.x, v0.x); fma2(o[1], p2.x, v0.y);
                    fma2(o[2], p2.x, v1.x); fma2(o[3], p2.x, v1.y);
                    fma2(o[4], p2.x, v2.x); fma2(o[5], p2.x, v2.y);
                    fma2(o[6], p2.x, v3.x); fma2(o[7], p2.x, v3.y);
                    ulonglong2 w0 = vb[(t0 + 1) * 32 + vidx];
                    ulonglong2 w1 = vb[(t0 + 1) * 32 + vidx + 1];
                    ulonglong2 w2 = vb[(t0 + 1) * 32 + vidx + 2];
                    ulonglong2 w3 = vb[(t0 + 1) * 32 + vidx + 3];
                    fma2(o[0], p2.y, w0.x); fma2(o[1], p2.y, w0.y);
                    fma2(o[2], p2.y, w1.x); fma2(o[3], p2.y, w1.y);
                    fma2(o[4], p2.y, w2.x); fma2(o[5], p2.y, w2.y);
                    fma2(o[6], p2.y, w3.x); fma2(o[7], p2.y, w3.y);
                }
            }
            __syncthreads();   // C: PV done -> buffers may be refilled

            if (it + 2 < ntiles) issue_tile(it + 2);
        }
    }

    // ---- store split partials ----
    {
        float* po = g_po + ((size_t)part * RR) * DVV + pr * DVV + pd;
#pragma unroll
        for (int i = 0; i < 4; i++) {
            float2 a  = unpack2(o[2 * i]);
            float2 bf = unpack2(o[2 * i + 1]);
            *(float4*)(po + 4 * i) = make_float4(a.x, a.y, bf.x, bf.y);
        }
        if (lane == 0) {
#pragma unroll
            for (int rr = 0; rr < 4; rr++) {
                g_pm[part * RR + R + rr] = m[rr];
                g_pl[part * RR + R + rr] = l[rr];
            }
        }
    }
}

extern "C" __global__ void __launch_bounds__(128)
attn_reduce_kernel(float* __restrict__ out)
{
    const int hkv = blockIdx.x;
    const int b   = blockIdx.y;
    const int r   = blockIdx.z;        // 0..15
    const int d   = threadIdx.x;       // 0..127
    const int pb  = (b * HKV + hkv) * NSPLIT;

    float M = -1e30f;
#pragma unroll
    for (int s = 0; s < NSPLIT; s++) M = fmaxf(M, g_pm[(pb + s) * RR + r]);

    float lt = 0.f;
    float acc = 0.f;
#pragma unroll
    for (int s = 0; s < NSPLIT; s++) {
        float mm = g_pm[(pb + s) * RR + r];
        float w  = __expf(mm - M);
        lt  += w * g_pl[(pb + s) * RR + r];
        acc += w * g_po[((size_t)(pb + s) * RR + r) * DVV + d];
    }

    const int m  = r & 3;
    const int gi = r >> 2;
    out[((size_t)((b * SQ + m) * HH + hkv * GG + gi)) * DVV + d] = acc / lt;
}

extern "C" void kernel_launch(void* const* d_in, const int* in_sizes, int n_in,
                              void* d_out, int out_size)
{
    const float* Q  = (const float*)d_in[0];
    const float* K  = (const float*)d_in[1];
    const float* V  = (const float*)d_in[2];
    const int*   sl = (const int*)d_in[3];

    cudaFuncSetAttribute(attn_split_kernel,
                         cudaFuncAttributeMaxDynamicSharedMemorySize, SMEM_BYTES);

    attn_split_kernel<<<dim3(NSPLIT, HKV, BB), NTHREADS, SMEM_BYTES>>>(Q, K, V, sl);
    attn_reduce_kernel<<<dim3(HKV, BB, RR), 128>>>((float*)d_out);
}

// round 7
// speedup vs baseline: 1.3546x; 1.3546x over previous
#include <cuda_runtime.h>
#include <cstdint>

#define BB 4
#define SQ 4
#define HH 32
#define HKV 8
#define GG 4
#define DD 128
#define DVV 128
#define SMAX 8192
#define RR 16
#define TT 32
#define NSPLIT 32
#define CHUNK (SMAX / NSPLIT)
#define NTHREADS 128
#define SCALE 0.08838834764831845f

// smem layout (bytes)
#define SMEM_Q_OFF 0
#define SMEM_K_OFF 8192
#define SMEM_V_OFF (8192 + 32768)
#define SMEM_P_OFF (8192 + 32768 + 32768)   // [4 warps][32 tok][4 rows] float = 2048
#define SMEM_BYTES (SMEM_P_OFF + 2048)

typedef unsigned long long u64;

__device__ __forceinline__ void fma2(u64& d, u64 a, u64 b) {
    asm("fma.rn.f32x2 %0, %1, %2, %0;" : "+l"(d) : "l"(a), "l"(b));
}
__device__ __forceinline__ void mul2(u64& d, u64 a) {
    asm("mul.rn.f32x2 %0, %0, %1;" : "+l"(d) : "l"(a));
}
__device__ __forceinline__ u64 pack2(float x) {
    u64 r; asm("mov.b64 %0, {%1, %1};" : "=l"(r) : "f"(x)); return r;
}
__device__ __forceinline__ float2 unpack2(u64 a) {
    float2 f; asm("mov.b64 {%0, %1}, %2;" : "=f"(f.x), "=f"(f.y) : "l"(a)); return f;
}

// split-K partial scratch (static device memory; no allocation)
__device__ float g_po[(size_t)BB * HKV * NSPLIT * RR * DVV];
__device__ float g_pm[BB * HKV * NSPLIT * RR];
__device__ float g_pl[BB * HKV * NSPLIT * RR];

extern "C" __global__ void __launch_bounds__(NTHREADS, 3)
attn_split_kernel(const float* __restrict__ Q, const float* __restrict__ K,
                  const float* __restrict__ V, const int* __restrict__ seqlens)
{
    extern __shared__ char smem[];
    float4* qs4 = (float4*)(smem + SMEM_Q_OFF);
    float4* ks4 = (float4*)(smem + SMEM_K_OFF);
    float4* vs4 = (float4*)(smem + SMEM_V_OFF);
    float*  sP  = (float*)(smem + SMEM_P_OFF);   // [wid][tok][4 rows]

    const int split = blockIdx.x;
    const int hkv   = blockIdx.y;
    const int b     = blockIdx.z;
    const int tid   = threadIdx.x;
    const int lane  = tid & 31;
    const int wid   = tid >> 5;

    const int L  = seqlens[b];
    const int c0 = split * CHUNK;
    int n_eff = L - c0;
    if (n_eff > CHUNK) n_eff = CHUNK;
    const int part = (b * HKV + hkv) * NSPLIT + split;

    // warp owns rows R..R+3 for the WHOLE pipeline (QK, softmax, PV)
    const int R = wid * 4;
    float* sPw = sP + wid * (TT * 4);

    // QK lane mapping: tp = token-pair, dh = dim-half
    const int tp = lane & 15;
    const int dh = lane >> 4;
    const int t0 = 2 * tp;

    float m[4], l[4];
#pragma unroll
    for (int i = 0; i < 4; i++) { m[i] = -1e30f; l[i] = 0.f; }
    // PV accumulators: 4 rows x 4 dims (dims lane*4 .. lane*4+3)
    u64 o[8];
#pragma unroll
    for (int i = 0; i < 8; i++) o[i] = 0ull;

    if (n_eff > 0) {
        // ---- Q (pre-scaled) into smem ----
#pragma unroll
        for (int i = 0; i < 4; i++) {
            int f  = i * NTHREADS + tid;
            int r  = f >> 5;
            int d4 = f & 31;
            int h  = hkv * GG + (r >> 2);
            int mm = r & 3;
            const float4 qv = *(const float4*)(Q + ((size_t)((b * SQ + mm) * HH + h)) * DD + d4 * 4);
            float4 qq;
            qq.x = qv.x * SCALE; qq.y = qv.y * SCALE;
            qq.z = qv.z * SCALE; qq.w = qv.w * SCALE;
            qs4[f] = qq;
        }

        const int ntiles = (n_eff + TT - 1) / TT;
        const size_t kvbase = ((size_t)b * SMAX * HKV + hkv) * DD;

        auto issue_tile = [&](int it) {
            const int jb   = c0 + it * TT;
            const int bufo = (it & 1) * (TT * 32);
#pragma unroll
            for (int i = 0; i < 8; i++) {
                int f  = i * NTHREADS + tid;   // 0..1023
                int t  = f >> 5;
                int d4 = f & 31;
                const float* gk = K + kvbase + (size_t)(jb + t) * (HKV * DD) + d4 * 4;
                const float* gv = V + kvbase + (size_t)(jb + t) * (HKV * DD) + d4 * 4;
                unsigned ka = (unsigned)__cvta_generic_to_shared(&ks4[bufo + t * 32 + (d4 ^ (t >> 1))]);
                unsigned va = (unsigned)__cvta_generic_to_shared(&vs4[bufo + t * 32 + d4]);
                asm volatile("cp.async.cg.shared.global [%0], [%1], 16;\n" :: "r"(ka), "l"(gk));
                asm volatile("cp.async.cg.shared.global [%0], [%1], 16;\n" :: "r"(va), "l"(gv));
            }
            asm volatile("cp.async.commit_group;\n" ::: "memory");
        };

        issue_tile(0);
        if (ntiles > 1) issue_tile(1);

        for (int it = 0; it < ntiles; ++it) {
            if (it < ntiles - 1) asm volatile("cp.async.wait_group 1;\n" ::: "memory");
            else                 asm volatile("cp.async.wait_group 0;\n" ::: "memory");
            __syncthreads();   // A: tile (and Q on it==0) visible

            const int jb   = c0 + it * TT;
            const int bufo = (it & 1) * (TT * 32);

            // ---- S = Q K^T : 4 rows x 2 tokens x d-half per thread ----
            u64 acc[4][2];
#pragma unroll
            for (int rr = 0; rr < 4; rr++) { acc[rr][0] = 0ull; acc[rr][1] = 0ull; }
            {
                const ulonglong2* kb = (const ulonglong2*)(ks4 + bufo);
                const ulonglong2* qb = (const ulonglong2*)qs4;
#pragma unroll
                for (int i = 0; i < 16; i++) {
                    const int d4  = dh * 16 + i;
                    const int col = d4 ^ tp;
                    ulonglong2 k0 = kb[t0 * 32 + col];
                    ulonglong2 k1 = kb[(t0 + 1) * 32 + col];
#pragma unroll
                    for (int rr = 0; rr < 4; rr++) {
                        ulonglong2 q = qb[(R + rr) * 32 + d4];
                        fma2(acc[rr][0], q.x, k0.x);
                        fma2(acc[rr][0], q.y, k0.y);
                        fma2(acc[rr][1], q.x, k1.x);
                        fma2(acc[rr][1], q.y, k1.y);
                    }
                }
            }

            // ---- in-warp online softmax for rows R..R+3 ----
            float p[4][2];
            {
                float s[4][2];
                bool  ok0 = true, ok1 = true;
#pragma unroll
                for (int rr = 0; rr < 4; rr++) {
#pragma unroll
                    for (int j = 0; j < 2; j++) {
                        float2 f = unpack2(acc[rr][j]);
                        float v  = f.x + f.y;
                        v += __shfl_xor_sync(0xffffffffu, v, 16);  // combine d-halves
                        s[rr][j] = v;
                    }
                }
                float mx[4];
#pragma unroll
                for (int rr = 0; rr < 4; rr++) {
                    const int lim = L - SQ + ((R + rr) & 3);
                    bool o0 = (jb + t0)     <= lim;
                    bool o1 = (jb + t0 + 1) <= lim;
                    if (rr == 3) { ok0 = o0; ok1 = o1; }  // rr=3 least restrictive? no: lim grows with rr
                    if (!o0) s[rr][0] = -1e30f;
                    if (!o1) s[rr][1] = -1e30f;
                    mx[rr] = fmaxf(s[rr][0], s[rr][1]);
                }
#pragma unroll
                for (int off = 8; off >= 1; off >>= 1) {
#pragma unroll
                    for (int rr = 0; rr < 4; rr++)
                        mx[rr] = fmaxf(mx[rr], __shfl_xor_sync(0xffffffffu, mx[rr], off));
                }
                float corr[4], sum[4];
#pragma unroll
                for (int rr = 0; rr < 4; rr++) {
                    float nm = fmaxf(m[rr], mx[rr]);
                    p[rr][0] = (s[rr][0] > -1e29f) ? __expf(s[rr][0] - nm) : 0.f;
                    p[rr][1] = (s[rr][1] > -1e29f) ? __expf(s[rr][1] - nm) : 0.f;
                    corr[rr] = __expf(m[rr] - nm);
                    m[rr]    = nm;
                    sum[rr]  = p[rr][0] + p[rr][1];
                }
#pragma unroll
                for (int off = 8; off >= 1; off >>= 1) {
#pragma unroll
                    for (int rr = 0; rr < 4; rr++)
                        sum[rr] += __shfl_xor_sync(0xffffffffu, sum[rr], off);
                }
#pragma unroll
                for (int rr = 0; rr < 4; rr++)
                    l[rr] = l[rr] * corr[rr] + sum[rr];

                // stage P (warp-private): [tok][4 rows]
                if (dh == 0) {
                    *(float4*)(sPw + t0 * 4)       = make_float4(p[0][0], p[1][0], p[2][0], p[3][0]);
                    *(float4*)(sPw + (t0 + 1) * 4) = make_float4(p[0][1], p[1][1], p[2][1], p[3][1]);
                }
                __syncwarp();

                // rescale accumulators
#pragma unroll
                for (int rr = 0; rr < 4; rr++) {
                    u64 cc = pack2(corr[rr]);
                    mul2(o[2 * rr],     cc);
                    mul2(o[2 * rr + 1], cc);
                }
            }

            // ---- O(rows R..R+3) += P V : lane owns dims lane*4..+3 ----
            {
                const ulonglong2* vb = (const ulonglong2*)(vs4 + bufo);
#pragma unroll 8
                for (int t = 0; t < TT; t++) {
                    float4 pv = *(const float4*)(sPw + t * 4);   // broadcast
                    ulonglong2 v = vb[t * 32 + lane];
                    u64 p0 = pack2(pv.x);
                    u64 p1 = pack2(pv.y);
                    u64 p2 = pack2(pv.z);
                    u64 p3 = pack2(pv.w);
                    fma2(o[0], p0, v.x); fma2(o[1], p0, v.y);
                    fma2(o[2], p1, v.x); fma2(o[3], p1, v.y);
                    fma2(o[4], p2, v.x); fma2(o[5], p2, v.y);
                    fma2(o[6], p3, v.x); fma2(o[7], p3, v.y);
                }
            }
            __syncthreads();   // C: all warps done with buffers

            if (it + 2 < ntiles) issue_tile(it + 2);
        }
    }

    // ---- store split partials: warp rows R..R+3, lane dims lane*4..+3 ----
    {
#pragma unroll
        for (int rr = 0; rr < 4; rr++) {
            float2 a  = unpack2(o[2 * rr]);
            float2 bf = unpack2(o[2 * rr + 1]);
            *(float4*)(g_po + ((size_t)part * RR + R + rr) * DVV + lane * 4) =
                make_float4(a.x, a.y, bf.x, bf.y);
        }
        if (lane == 0) {
#pragma unroll
            for (int rr = 0; rr < 4; rr++) {
                g_pm[part * RR + R + rr] = m[rr];
                g_pl[part * RR + R + rr] = l[rr];
            }
        }
    }
}

extern "C" __global__ void __launch_bounds__(512)
attn_reduce_kernel(float* __restrict__ out)
{
    __shared__ float sM4[4], sL4[4], sAcc[4][128];

    const int hkv = blockIdx.x;
    const int b   = blockIdx.y;
    const int r   = blockIdx.z;          // 0..15
    const int tid = threadIdx.x;
    const int sg  = tid >> 7;            // 0..3 : split group
    const int d   = tid & 127;
    const int pb  = (b * HKV + hkv) * NSPLIT;

    float M = -1e30f;
#pragma unroll
    for (int s = 0; s < 8; s++)
        M = fmaxf(M, g_pm[(pb + sg * 8 + s) * RR + r]);
    if (d == 0) sM4[sg] = M;
    __syncthreads();
    M = fmaxf(fmaxf(sM4[0], sM4[1]), fmaxf(sM4[2], sM4[3]));

    float lt = 0.f, acc = 0.f;
#pragma unroll
    for (int s = 0; s < 8; s++) {
        const int ss = pb + sg * 8 + s;
        float w = __expf(g_pm[ss * RR + r] - M);
        lt  += w * g_pl[ss * RR + r];
        acc += w * g_po[((size_t)ss * RR + r) * DVV + d];
    }
    sAcc[sg][d] = acc;
    if (d == 0) sL4[sg] = lt;
    __syncthreads();

    if (sg == 0) {
        acc = sAcc[0][d] + sAcc[1][d] + sAcc[2][d] + sAcc[3][d];
        lt  = sL4[0] + sL4[1] + sL4[2] + sL4[3];
        const int mq = r & 3;
        const int gi = r >> 2;
        out[((size_t)((b * SQ + mq) * HH + hkv * GG + gi)) * DVV + d] = acc / lt;
    }
}

extern "C" void kernel_launch(void* const* d_in, const int* in_sizes, int n_in,
                              void* d_out, int out_size)
{
    const float* Q  = (const float*)d_in[0];
    const float* K  = (const float*)d_in[1];
    const float* V  = (const float*)d_in[2];
    const int*   sl = (const int*)d_in[3];

    cudaFuncSetAttribute(attn_split_kernel,
                         cudaFuncAttributeMaxDynamicSharedMemorySize, SMEM_BYTES);

    attn_split_kernel<<<dim3(NSPLIT, HKV, BB), NTHREADS, SMEM_BYTES>>>(Q, K, V, sl);
    attn_reduce_kernel<<<dim3(HKV, BB, RR), 512>>>((float*)d_out);
}